// round 16
// baseline (speedup 1.0000x reference)
#include <cuda_runtime.h>

// RotateMyLayer: STN affine bilinear warp of ROIs from a batched feature map.
// feature_map: [8, 160, 160, 256] f32
// transform_matrixs: [10, 6] f32
// box_masks: [10] i32 (batch index per roi)
// box_widths: [10] i32
// out: [10, 8, 384, 256] f32

#define OUT_H   8
#define MAX_W   384
#define MAX_ROI 10
#define FH      160
#define FW      160
#define NC      256
#define NC4     (NC / 4)    // 64 float4 per pixel

// Full independent bilinear sample: 8 LDG.128, blend, 2 STG.128.
__device__ __forceinline__ void sample_one(
    float x, float y,
    const float4* __restrict__ fmBase,   // fm + b*FH*FW*NC4 + lane
    float4* __restrict__ op)             // out tuple base + lane
{
    const float x0f = floorf(x);
    const float y0f = floorf(y);
    const int x0 = min(max((int)x0f,     0), FW - 1);
    const int x1 = min(max((int)x0f + 1, 0), FW - 1);
    const int y0 = min(max((int)y0f,     0), FH - 1);
    const int y1 = min(max((int)y0f + 1, 0), FH - 1);

    const float4* pa = fmBase + (y0 * FW + x0) * NC4;
    const int dRow = (y1 - y0) * (FW * NC4);
    const int dCol = (x1 - x0) * NC4;

    const float4 Ia0 = pa[0];
    const float4 Ia1 = pa[32];
    const float4 Ib0 = pa[dRow];
    const float4 Ib1 = pa[dRow + 32];
    const float4 Ic0 = pa[dCol];
    const float4 Ic1 = pa[dCol + 32];
    const float4 Id0 = pa[dRow + dCol];
    const float4 Id1 = pa[dRow + dCol + 32];

    const float dx = x - x0f;
    const float dy = y - y0f;
    const float wa = (1.0f - dx) * (1.0f - dy);
    const float wb = (1.0f - dx) * dy;
    const float wc = dx * (1.0f - dy);
    const float wd = dx * dy;

    float4 r0, r1;
    r0.x = wa * Ia0.x + wb * Ib0.x + wc * Ic0.x + wd * Id0.x;
    r0.y = wa * Ia0.y + wb * Ib0.y + wc * Ic0.y + wd * Id0.y;
    r0.z = wa * Ia0.z + wb * Ib0.z + wc * Ic0.z + wd * Id0.z;
    r0.w = wa * Ia0.w + wb * Ib0.w + wc * Ic0.w + wd * Id0.w;
    r1.x = wa * Ia1.x + wb * Ib1.x + wc * Ic1.x + wd * Id1.x;
    r1.y = wa * Ia1.y + wb * Ib1.y + wc * Ic1.y + wd * Id1.y;
    r1.z = wa * Ia1.z + wb * Ib1.z + wc * Ic1.z + wd * Id1.z;
    r1.w = wa * Ia1.w + wb * Ib1.w + wc * Ic1.w + wd * Id1.w;

    op[0]  = r0;
    op[32] = r1;
}

// Each warp handles an adjacent j-pair (j0, j0+1) of the same (roi, i).
// ~half of adjacent pairs fall in the SAME bilinear cell (x step = cx ~0.3px);
// those pairs load the 4 corner pixels ONCE and blend twice, cutting corner
// L1 wavefronts ~24% overall — the L1 replay-rate ceiling is the plateau.
__global__ __launch_bounds__(128, 16) void stn_warp_kernel(
    const float* __restrict__ fm,
    const float* __restrict__ thetas,
    const int*   __restrict__ masks,
    const int*   __restrict__ widths,
    float*       __restrict__ out)
{
    const int warp = threadIdx.x >> 5;
    const int lane = threadIdx.x & 31;
    const int j0   = (blockIdx.x * 4 + warp) * 2;   // 0,2,..,382
    const int t    = blockIdx.y;                    // 0..79 (= roi*8 + i)
    const int i    = t & 7;
    const int roi  = t >> 3;

    float4* op0 = reinterpret_cast<float4*>(out)
                + (t * MAX_W + j0) * NC4 + lane;
    float4* op1 = op0 + NC4;

    const int w = __ldg(&widths[roi]);
    if (j0 >= w) {                      // j0 >= w implies j0+1 >= w
        const float4 z = make_float4(0.f, 0.f, 0.f, 0.f);
        op0[0] = z; op0[32] = z;
        op1[0] = z; op1[32] = z;
        return;
    }

    const float2* th = reinterpret_cast<const float2*>(thetas + roi * 6);
    const float2 th0 = __ldg(&th[0]);   // t00, t01
    const float2 th1 = __ldg(&th[1]);   // t02, t10
    const float2 th2 = __ldg(&th[2]);   // t11, t12
    const int    b   = __ldg(&masks[roi]);

    // Fused affine: x = cx*j + xb, y = cy*j + yb (shared by the pair).
    const float denom = (float)((w - 1) > 1 ? (w - 1) : 1);
    const float rden  = __frcp_rn(denom);
    const float y_t   = -1.0f + 2.0f * (float)i * (1.0f / 7.0f);

    const float cx = (2.0f * (float)(FW / 2)) * th0.x * rden;
    const float cy = (2.0f * (float)(FH / 2)) * th1.y * rden;
    const float xb = (float)(FW / 2) * (th0.y * y_t + th1.x - th0.x + 1.0f);
    const float yb = (float)(FH / 2) * (th2.x * y_t + th2.y - th1.y + 1.0f);

    const float4* fmBase = reinterpret_cast<const float4*>(fm)
                         + (b * (FH * FW)) * NC4 + lane;

    const float xA = cx * (float)j0 + xb;
    const float yA = cy * (float)j0 + yb;

    if (j0 + 1 >= w) {                  // only j0 valid
        sample_one(xA, yA, fmBase, op0);
        const float4 z = make_float4(0.f, 0.f, 0.f, 0.f);
        op1[0] = z; op1[32] = z;
        return;
    }

    const float xB = xA + cx;
    const float yB = yA + cy;

    const float xAf = floorf(xA), yAf = floorf(yA);
    const float xBf = floorf(xB), yBf = floorf(yB);

    if (xAf == xBf && yAf == yBf) {
        // --- Shared-cell fast path: 8 loads serve BOTH tuples. ---
        const int x0 = min(max((int)xAf,     0), FW - 1);
        const int x1 = min(max((int)xAf + 1, 0), FW - 1);
        const int y0 = min(max((int)yAf,     0), FH - 1);
        const int y1 = min(max((int)yAf + 1, 0), FH - 1);

        const float4* pa = fmBase + (y0 * FW + x0) * NC4;
        const int dRow = (y1 - y0) * (FW * NC4);
        const int dCol = (x1 - x0) * NC4;

        const float dxA = xA - xAf, dyA = yA - yAf;
        const float dxB = xB - xAf, dyB = yB - yAf;
        const float waA = (1.0f - dxA) * (1.0f - dyA);
        const float wbA = (1.0f - dxA) * dyA;
        const float wcA = dxA * (1.0f - dyA);
        const float wdA = dxA * dyA;
        const float waB = (1.0f - dxB) * (1.0f - dyB);
        const float wbB = (1.0f - dxB) * dyB;
        const float wcB = dxB * (1.0f - dyB);
        const float wdB = dxB * dyB;

        // Channel half 0 (payload 16 regs, retired before half 1).
        {
            const float4 Ia = pa[0];
            const float4 Ib = pa[dRow];
            const float4 Ic = pa[dCol];
            const float4 Id = pa[dRow + dCol];
            float4 rA, rB;
            rA.x = waA*Ia.x + wbA*Ib.x + wcA*Ic.x + wdA*Id.x;
            rA.y = waA*Ia.y + wbA*Ib.y + wcA*Ic.y + wdA*Id.y;
            rA.z = waA*Ia.z + wbA*Ib.z + wcA*Ic.z + wdA*Id.z;
            rA.w = waA*Ia.w + wbA*Ib.w + wcA*Ic.w + wdA*Id.w;
            rB.x = waB*Ia.x + wbB*Ib.x + wcB*Ic.x + wdB*Id.x;
            rB.y = waB*Ia.y + wbB*Ib.y + wcB*Ic.y + wdB*Id.y;
            rB.z = waB*Ia.z + wbB*Ib.z + wcB*Ic.z + wdB*Id.z;
            rB.w = waB*Ia.w + wbB*Ib.w + wcB*Ic.w + wdB*Id.w;
            op0[0] = rA;
            op1[0] = rB;
        }
        // Channel half 1.
        {
            const float4 Ia = pa[32];
            const float4 Ib = pa[dRow + 32];
            const float4 Ic = pa[dCol + 32];
            const float4 Id = pa[dRow + dCol + 32];
            float4 rA, rB;
            rA.x = waA*Ia.x + wbA*Ib.x + wcA*Ic.x + wdA*Id.x;
            rA.y = waA*Ia.y + wbA*Ib.y + wcA*Ic.y + wdA*Id.y;
            rA.z = waA*Ia.z + wbA*Ib.z + wcA*Ic.z + wdA*Id.z;
            rA.w = waA*Ia.w + wbA*Ib.w + wcA*Ic.w + wdA*Id.w;
            rB.x = waB*Ia.x + wbB*Ib.x + wcB*Ic.x + wdB*Id.x;
            rB.y = waB*Ia.y + wbB*Ib.y + wcB*Ic.y + wdB*Id.y;
            rB.z = waB*Ia.z + wbB*Ib.z + wcB*Ic.z + wdB*Id.z;
            rB.w = waB*Ia.w + wbB*Ib.w + wcB*Ic.w + wdB*Id.w;
            op0[32] = rA;
            op1[32] = rB;
        }
    } else {
        // --- Distinct cells: two independent samples (registers reused). ---
        sample_one(xA, yA, fmBase, op0);
        sample_one(xB, yB, fmBase, op1);
    }
}

extern "C" void kernel_launch(void* const* d_in, const int* in_sizes, int n_in,
                              void* d_out, int out_size)
{
    const float* fm     = (const float*)d_in[0];
    const float* thetas = (const float*)d_in[1];
    const int*   masks  = (const int*)d_in[2];
    const int*   widths = (const int*)d_in[3];
    float*       out    = (float*)d_out;

    dim3 grid(48, MAX_ROI * OUT_H);   // (48, 80): 4 warps x j-pairs per block
    stn_warp_kernel<<<grid, 128>>>(fm, thetas, masks, widths, out);
}

// round 17
// speedup vs baseline: 1.1910x; 1.1910x over previous
#include <cuda_runtime.h>

// RotateMyLayer: STN affine bilinear warp of ROIs from a batched feature map.
// feature_map: [8, 160, 160, 256] f32
// transform_matrixs: [10, 6] f32
// box_masks: [10] i32 (batch index per roi)
// box_widths: [10] i32
// out: [10, 8, 384, 256] f32

#define OUT_H   8
#define MAX_W   384
#define MAX_ROI 10
#define FH      160
#define FW      160
#define NC      256
#define NC4     (NC / 4)    // 64 float4 per pixel

// R4 body (proven best) at 256 threads/block: 8 adjacent j per block doubles
// intra-block corner-pixel L1 sharing and halves block dispatch events,
// with identical threads/SM (8 blocks x 256 = 2048).
__global__ __launch_bounds__(256, 8) void stn_warp_kernel(
    const float* __restrict__ fm,
    const float* __restrict__ thetas,
    const int*   __restrict__ masks,
    const int*   __restrict__ widths,
    float*       __restrict__ out)
{
    // One warp per (roi, i, j) tuple; each lane handles 8 channels (2 float4).
    // grid = (48, 80), block = 256 (8 warps = 8 adjacent j-positions).
    const int warp = threadIdx.x >> 5;
    const int lane = threadIdx.x & 31;
    const int j    = blockIdx.x * 8 + warp;   // 0..383
    const int t    = blockIdx.y;              // 0..79  (= roi*8 + i)
    const int i    = t & 7;
    const int roi  = t >> 3;

    // 32-bit offsets everywhere (fm = 26M float4, out = 2M float4).
    float4* op = reinterpret_cast<float4*>(out)
               + (t * MAX_W + j) * NC4 + lane;

    const int w = __ldg(&widths[roi]);
    if (j >= w) {
        const float4 z = make_float4(0.f, 0.f, 0.f, 0.f);
        op[0]  = z;
        op[32] = z;
        return;
    }

    const float2* th = reinterpret_cast<const float2*>(thetas + roi * 6);
    const float2 th0 = __ldg(&th[0]);   // t00, t01
    const float2 th1 = __ldg(&th[1]);   // t02, t10
    const float2 th2 = __ldg(&th[2]);   // t11, t12
    const int    b   = __ldg(&masks[roi]);

    const float denom = (float)((w - 1) > 1 ? (w - 1) : 1);
    const float x_t = -1.0f + 2.0f * __fdividef((float)j, denom);
    const float y_t = -1.0f + 2.0f * (float)i * (1.0f / 7.0f);

    const float xs = th0.x * x_t + th0.y * y_t + th1.x;
    const float ys = th1.y * x_t + th2.x * y_t + th2.y;
    const float x  = (xs + 1.0f) * (0.5f * (float)FW);
    const float y  = (ys + 1.0f) * (0.5f * (float)FH);

    const float x0f = floorf(x);
    const float y0f = floorf(y);
    const int x0 = min(max((int)x0f,     0), FW - 1);
    const int x1 = min(max((int)x0f + 1, 0), FW - 1);
    const int y0 = min(max((int)y0f,     0), FH - 1);
    const int y1 = min(max((int)y0f + 1, 0), FH - 1);

    // Addresses first -> issue all 8 LDG.128 ASAP.
    const float4* pa = reinterpret_cast<const float4*>(fm)
        + (b * (FH * FW) + y0 * FW + x0) * NC4 + lane;
    const int dRow = (y1 - y0) * (FW * NC4);   // 0 or FW*NC4
    const int dCol = (x1 - x0) * NC4;          // 0 or NC4

    const float4 Ia0 = pa[0];
    const float4 Ia1 = pa[32];
    const float4 Ib0 = pa[dRow];
    const float4 Ib1 = pa[dRow + 32];
    const float4 Ic0 = pa[dCol];
    const float4 Ic1 = pa[dCol + 32];
    const float4 Id0 = pa[dRow + dCol];
    const float4 Id1 = pa[dRow + dCol + 32];

    // Weight math lives in the load shadow.
    const float dx = x - x0f;
    const float dy = y - y0f;
    const float wa = (1.0f - dx) * (1.0f - dy);
    const float wb = (1.0f - dx) * dy;
    const float wc = dx * (1.0f - dy);
    const float wd = dx * dy;

    float4 r0, r1;
    r0.x = wa * Ia0.x + wb * Ib0.x + wc * Ic0.x + wd * Id0.x;
    r0.y = wa * Ia0.y + wb * Ib0.y + wc * Ic0.y + wd * Id0.y;
    r0.z = wa * Ia0.z + wb * Ib0.z + wc * Ic0.z + wd * Id0.z;
    r0.w = wa * Ia0.w + wb * Ib0.w + wc * Ic0.w + wd * Id0.w;
    r1.x = wa * Ia1.x + wb * Ib1.x + wc * Ic1.x + wd * Id1.x;
    r1.y = wa * Ia1.y + wb * Ib1.y + wc * Ic1.y + wd * Id1.y;
    r1.z = wa * Ia1.z + wb * Ib1.z + wc * Ic1.z + wd * Id1.z;
    r1.w = wa * Ia1.w + wb * Ib1.w + wc * Ic1.w + wd * Id1.w;

    op[0]  = r0;
    op[32] = r1;
}

extern "C" void kernel_launch(void* const* d_in, const int* in_sizes, int n_in,
                              void* d_out, int out_size)
{
    const float* fm     = (const float*)d_in[0];
    const float* thetas = (const float*)d_in[1];
    const int*   masks  = (const int*)d_in[2];
    const int*   widths = (const int*)d_in[3];
    float*       out    = (float*)d_out;

    dim3 grid(MAX_W / 8, MAX_ROI * OUT_H);   // (48, 80)
    stn_warp_kernel<<<grid, 256>>>(fm, thetas, masks, widths, out);
}